// round 2
// baseline (speedup 1.0000x reference)
#include <cuda_runtime.h>
#include <math.h>

#define HWSZ 9216
#define GH 96
#define GW 96
#define NTHREADS 512

// scratch for the 16 directed distances (8 samples x 2 directions)
__device__ float g_dir[16];

// One block per (sample, direction).
//   dir 0: src = A & ~B, tgt = B   (distA)
//   dir 1: src = ~A & B, tgt = A   (distB)
// Exact Euclidean distance transform of tgt (separable, integer),
// then max of sqrt(D2) over src pixels.
__global__ __launch_bounds__(NTHREADS) void hausdorff_dir_kernel(
    const float* __restrict__ predict,
    const float* __restrict__ target)
{
    const int n   = blockIdx.x >> 1;
    const int dir = blockIdx.x & 1;
    const int tid = threadIdx.x;

    __shared__ unsigned char  s_tgt[HWSZ];        // 9216 B
    __shared__ unsigned int   s_srcbits[HWSZ/32]; // 1152 B
    __shared__ unsigned short s_cm2[HWSZ];        // 18432 B (squared 1D column distance)
    __shared__ int            s_tgtcount;
    __shared__ int            s_warpmax[NTHREADS/32];

    if (tid == 0) s_tgtcount = 0;
    __syncthreads();

    const float* pa = predict + n * HWSZ;
    const float* pb = target  + n * HWSZ;

    // ---- Phase 1: build masks ----
    // 9216 / 512 = 18 full iterations; every lane always active.
    int tcount = 0;
    #pragma unroll 2
    for (int p = tid; p < HWSZ; p += NTHREADS) {
        bool a = rintf(pa[p]) > 0.5f;   // matches jnp.round (half-to-even)
        bool b = rintf(pb[p]) > 0.5f;
        bool t = dir ? a : b;
        bool s = dir ? ((!a) && b) : (a && (!b));
        s_tgt[p] = (unsigned char)t;
        unsigned tb = __ballot_sync(0xffffffffu, t);
        unsigned sb = __ballot_sync(0xffffffffu, s);
        if ((tid & 31) == 0) {
            s_srcbits[p >> 5] = sb;     // p stride 512 keeps word alignment exact
            tcount += __popc(tb);
        }
    }
    if ((tid & 31) == 0 && tcount) atomicAdd(&s_tgtcount, tcount);
    __syncthreads();

    // ---- Phase 2: per-column 1D distance (forward + backward sweep) ----
    if (tid < GW) {
        const int j = tid;
        int d = 255;
        // forward: store running distance (not yet squared)
        for (int i = 0; i < GH; i++) {
            d = s_tgt[i * GW + j] ? 0 : (d < 255 ? d + 1 : 255);
            s_cm2[i * GW + j] = (unsigned short)d;
        }
        // backward: merge, then square
        d = 255;
        for (int i = GH - 1; i >= 0; i--) {
            d = s_tgt[i * GW + j] ? 0 : (d < 255 ? d + 1 : 255);
            int v = min((int)s_cm2[i * GW + j], d);
            s_cm2[i * GW + j] = (unsigned short)(v * v);  // <= 65025, fits u16
        }
    }
    __syncthreads();

    // ---- Phase 3: row pass D2(i,j) = min_j' (j-j')^2 + cm2(i,j'); masked max ----
    int maxd2 = -1;
    for (int p = tid; p < HWSZ; p += NTHREADS) {
        const int i = p / GW;
        const int j = p - i * GW;
        const unsigned short* row = s_cm2 + i * GW;  // warp lanes share i -> broadcast loads
        int best = 0x7fffffff;
        #pragma unroll 8
        for (int jp = 0; jp < GW; jp++) {
            int dj = j - jp;
            best = min(best, dj * dj + (int)row[jp]);
        }
        if ((s_srcbits[p >> 5] >> (p & 31)) & 1u)
            maxd2 = max(maxd2, best);
    }

    // ---- Phase 4: block max-reduction ----
    #pragma unroll
    for (int off = 16; off > 0; off >>= 1)
        maxd2 = max(maxd2, __shfl_xor_sync(0xffffffffu, maxd2, off));
    if ((tid & 31) == 0) s_warpmax[tid >> 5] = maxd2;
    __syncthreads();

    if (tid == 0) {
        int m = -1;
        #pragma unroll
        for (int w = 0; w < NTHREADS / 32; w++) m = max(m, s_warpmax[w]);
        float val;
        if (m < 0) {
            val = 0.0f;                       // src empty
        } else if (s_tgtcount == 0) {
            val = 1e9f;                       // src nonempty, tgt empty (BIG)
        } else {
            val = sqrtf((float)m) * (1.0f / 96.0f);  // normalized grid scale
        }
        g_dir[blockIdx.x] = val;
    }
}

__global__ void hausdorff_finalize(float* __restrict__ out)
{
    float s = 0.0f;
    #pragma unroll
    for (int n = 0; n < 8; n++)
        s += fmaxf(g_dir[2 * n], g_dir[2 * n + 1]);
    out[0] = s * 0.125f;
}

extern "C" void kernel_launch(void* const* d_in, const int* in_sizes, int n_in,
                              void* d_out, int out_size)
{
    const float* predict = (const float*)d_in[0];
    const float* target  = (const float*)d_in[1];
    hausdorff_dir_kernel<<<16, NTHREADS>>>(predict, target);
    hausdorff_finalize<<<1, 1>>>((float*)d_out);
}

// round 3
// speedup vs baseline: 2.2635x; 2.2635x over previous
#include <cuda_runtime.h>
#include <math.h>

#define HWSZ 9216
#define GH 96
#define GW 96
#define NTHREADS 512
#define NBLOCKS 16

// scratch for the 16 directed distances (8 samples x 2 directions)
__device__ float    g_dir[NBLOCKS];
__device__ unsigned g_count = 0;   // self-resetting completion counter

// One block per (sample, direction).
//   dir 0: src = A & ~B, tgt = B   (distA)
//   dir 1: src = ~A & B, tgt = A   (distB)
// Exact separable EDT of tgt (integer), then max over src pixels with an
// early-exit ring search in the row dimension (exact: dj^2 monotone in r).
__global__ __launch_bounds__(NTHREADS) void hausdorff_dir_kernel(
    const float* __restrict__ predict,
    const float* __restrict__ target,
    float* __restrict__ out)
{
    const int n   = blockIdx.x >> 1;
    const int dir = blockIdx.x & 1;
    const int tid = threadIdx.x;

    __shared__ unsigned char  s_tgt[HWSZ];         // 9216 B
    __shared__ unsigned int   s_srcbits[HWSZ/32];  // 1152 B
    __shared__ unsigned short s_f[HWSZ];           // fwd col dist -> squared col dist
    __shared__ unsigned short s_bk[HWSZ];          // bwd col dist
    __shared__ int            s_tgtcount;
    __shared__ int            s_warpmax[NTHREADS/32];

    if (tid == 0) s_tgtcount = 0;
    __syncthreads();

    const float* pa = predict + n * HWSZ;
    const float* pb = target  + n * HWSZ;

    // ---- Phase 1: build masks (9216/512 = 18 full iterations, no tail) ----
    int tcount = 0;
    #pragma unroll 3
    for (int p = tid; p < HWSZ; p += NTHREADS) {
        bool a = rintf(pa[p]) > 0.5f;   // matches jnp.round (half-to-even)
        bool b = rintf(pb[p]) > 0.5f;
        bool t = dir ? a : b;
        bool s = dir ? ((!a) && b) : (a && (!b));
        s_tgt[p] = (unsigned char)t;
        unsigned tb = __ballot_sync(0xffffffffu, t);
        unsigned sb = __ballot_sync(0xffffffffu, s);
        if ((tid & 31) == 0) {
            s_srcbits[p >> 5] = sb;     // stride 512 keeps 32-bit word alignment
            tcount += __popc(tb);
        }
    }
    if ((tid & 31) == 0 && tcount) atomicAdd(&s_tgtcount, tcount);
    __syncthreads();

    // ---- Phase 2a: independent forward/backward 1D column sweeps ----
    if (tid < GW) {                       // forward (rows 0..95)
        const int j = tid;
        int d = 255;
        #pragma unroll 4
        for (int i = 0; i < GH; i++) {
            d = s_tgt[i * GW + j] ? 0 : min(d + 1, 255);
            s_f[i * GW + j] = (unsigned short)d;
        }
    } else if (tid < 2 * GW) {            // backward (rows 95..0)
        const int j = tid - GW;
        int d = 255;
        #pragma unroll 4
        for (int i = GH - 1; i >= 0; i--) {
            d = s_tgt[i * GW + j] ? 0 : min(d + 1, 255);
            s_bk[i * GW + j] = (unsigned short)d;
        }
    }
    __syncthreads();

    // ---- Phase 2b: merge + square (all threads) ----
    #pragma unroll 3
    for (int p = tid; p < HWSZ; p += NTHREADS) {
        int v = min((int)s_f[p], (int)s_bk[p]);
        s_f[p] = (unsigned short)(v * v);   // <= 65025, fits u16
    }
    __syncthreads();

    // ---- Phase 3: row pass with early-exit ring search, src pixels only ----
    int maxd2 = -1;
    for (int p = tid; p < HWSZ; p += NTHREADS) {
        if (!((s_srcbits[p >> 5] >> (p & 31)) & 1u)) continue;
        const int i = p / GW;
        const int j = p - i * GW;
        const unsigned short* row = s_f + i * GW;
        int best = (int)row[j];
        for (int r = 1; r < GW && r * r < best; r++) {
            int rr = r * r;
            if (j >= r)     best = min(best, rr + (int)row[j - r]);
            if (j + r < GW) best = min(best, rr + (int)row[j + r]);
        }
        maxd2 = max(maxd2, best);
    }

    // ---- Phase 4: block max-reduction ----
    #pragma unroll
    for (int off = 16; off > 0; off >>= 1)
        maxd2 = max(maxd2, __shfl_xor_sync(0xffffffffu, maxd2, off));
    if ((tid & 31) == 0) s_warpmax[tid >> 5] = maxd2;
    __syncthreads();

    if (tid == 0) {
        int m = -1;
        #pragma unroll
        for (int w = 0; w < NTHREADS / 32; w++) m = max(m, s_warpmax[w]);
        float val;
        if (m < 0)                   val = 0.0f;    // src empty
        else if (s_tgtcount == 0)    val = 1e9f;    // src nonempty, tgt empty
        else                         val = sqrtf((float)m) * (1.0f / 96.0f);
        g_dir[blockIdx.x] = val;

        // ---- fused finalize: last block to arrive computes the mean ----
        __threadfence();
        unsigned done = atomicAdd(&g_count, 1);
        if (done == NBLOCKS - 1) {
            g_count = 0;                       // reset for next graph replay
            __threadfence();
            const volatile float* gd = g_dir;
            float s = 0.0f;
            #pragma unroll
            for (int k = 0; k < 8; k++)
                s += fmaxf(gd[2 * k], gd[2 * k + 1]);
            out[0] = s * 0.125f;
        }
    }
}

extern "C" void kernel_launch(void* const* d_in, const int* in_sizes, int n_in,
                              void* d_out, int out_size)
{
    const float* predict = (const float*)d_in[0];
    const float* target  = (const float*)d_in[1];
    hausdorff_dir_kernel<<<NBLOCKS, NTHREADS>>>(predict, target, (float*)d_out);
}